// round 1
// baseline (speedup 1.0000x reference)
#include <cuda_runtime.h>
#include <cuda_bf16.h>
#include <math.h>

// Problem constants
#define BB 4
#define CC 64
#define OO 64
#define HH 128
#define WW 128
#define HW (HH*WW)
#define K2 9

// Scratch (device globals; no allocation allowed)
__device__ float g_wdef_t[K2 * CC * OO];      // [k][c][o]
__device__ float g_woff_t[CC * 27 * K2];      // [c][oc][k]  (27 output chans, 9 taps each)
__device__ int4   g_idx[BB * K2 * HW];        // 4 clamped flat indices per (b,k,pix)
__device__ float4 g_wgt[BB * K2 * HW];        // 4 bilinear weights (mask & validity folded)

// ---------------------------------------------------------------------------
// Kernel W: transpose weights into fast layouts
// ---------------------------------------------------------------------------
__global__ void ktranspose(const float* __restrict__ w_off,
                           const float* __restrict__ w_def) {
    int i = blockIdx.x * 256 + threadIdx.x;
    // woff_t[c*243 + oc*9 + k] = w_off[oc*576 + c*9 + k]
    if (i < CC * 27 * K2) {
        int c = i / (27 * K2);
        int r = i % (27 * K2);
        int oc = r / K2;
        int k  = r % K2;
        g_woff_t[i] = w_off[oc * (CC * K2) + c * K2 + k];
    }
    // wdef_t[k*4096 + c*64 + o] = w_def[o*576 + c*9 + k]
    if (i < K2 * CC * OO) {
        int k = i / (CC * OO);
        int r = i % (CC * OO);
        int c = r / OO;
        int o = r % OO;
        g_wdef_t[i] = w_def[o * (CC * K2) + c * K2 + k];
    }
}

// ---------------------------------------------------------------------------
// Kernel A: 3x3 offset conv (27 ch) + bilinear record construction
// grid: (H, B), block: 128 threads (one pixel per thread along a row)
// ---------------------------------------------------------------------------
__global__ __launch_bounds__(WW) void koffset(const float* __restrict__ feat,
                                              const float* __restrict__ b_off) {
    const int w = threadIdx.x;
    const int h = blockIdx.x;
    const int b = blockIdx.y;

    __shared__ float fs[3][132];        // 3 feat rows, +1 left pad, x in [0..129]
    __shared__ float wsm[27 * 12];      // per-channel weight slice, padded stride 12

    float acc[27];
#pragma unroll
    for (int i = 0; i < 27; i++) acc[i] = 0.f;

    const float* fb = feat + (size_t)b * CC * HW;

    for (int c = 0; c < CC; c++) {
        // stage weights for this input channel: 243 contiguous floats
        for (int i = threadIdx.x; i < 27 * K2; i += WW) {
            int oc = i / K2, k = i % K2;
            wsm[oc * 12 + k] = g_woff_t[c * (27 * K2) + i];
        }
        // stage 3 feat rows (zero-padded top/bottom)
#pragma unroll
        for (int r = 0; r < 3; r++) {
            int y = h + r - 1;
            float v = (y >= 0 && y < HH) ? fb[c * HW + y * WW + w] : 0.f;
            fs[r][w + 1] = v;
        }
        if (w == 0)  { fs[0][0]   = 0.f; fs[1][0]   = 0.f; fs[2][0]   = 0.f; }
        if (w == WW-1){ fs[0][129] = 0.f; fs[1][129] = 0.f; fs[2][129] = 0.f; }
        __syncthreads();

        float v[9];
#pragma unroll
        for (int ky = 0; ky < 3; ky++)
#pragma unroll
            for (int kx = 0; kx < 3; kx++)
                v[ky * 3 + kx] = fs[ky][w + kx];

#pragma unroll
        for (int oc = 0; oc < 27; oc++) {
            float s = acc[oc];
#pragma unroll
            for (int k = 0; k < 9; k++) s += v[k] * wsm[oc * 12 + k];
            acc[oc] = s;
        }
        __syncthreads();
    }

    // epilogue: bias, split into (off_x, off_y, mask), build bilinear records
    const int pix = h * WW + w;
#pragma unroll
    for (int k = 0; k < K2; k++) {
        float ox = acc[k]      + b_off[k];
        float oy = acc[9 + k]  + b_off[9 + k];
        float mm = acc[18 + k] + b_off[18 + k];
        float mask = 1.f / (1.f + expf(-mm));

        float ys = (float)h + (float)(k / 3 - 1) + oy;
        float xs = (float)w + (float)(k % 3 - 1) + ox;
        float y0f = floorf(ys), x0f = floorf(xs);
        float wy1 = ys - y0f, wx1 = xs - x0f;
        float wy0 = 1.f - wy1, wx0 = 1.f - wx1;
        int y0 = (int)y0f, x0 = (int)x0f;
        int y1 = y0 + 1,  x1 = x0 + 1;

        float vy0 = (y0 >= 0 && y0 < HH) ? 1.f : 0.f;
        float vy1 = (y1 >= 0 && y1 < HH) ? 1.f : 0.f;
        float vx0 = (x0 >= 0 && x0 < WW) ? 1.f : 0.f;
        float vx1 = (x1 >= 0 && x1 < WW) ? 1.f : 0.f;

        int cy0 = min(max(y0, 0), HH - 1);
        int cy1 = min(max(y1, 0), HH - 1);
        int cx0 = min(max(x0, 0), WW - 1);
        int cx1 = min(max(x1, 0), WW - 1);

        int4 ii;
        ii.x = cy0 * WW + cx0;
        ii.y = cy0 * WW + cx1;
        ii.z = cy1 * WW + cx0;
        ii.w = cy1 * WW + cx1;
        float4 ww;
        ww.x = wy0 * wx0 * mask * vy0 * vx0;
        ww.y = wy0 * wx1 * mask * vy0 * vx1;
        ww.z = wy1 * wx0 * mask * vy1 * vx0;
        ww.w = wy1 * wx1 * mask * vy1 * vx1;

        int rid = (b * K2 + k) * HW + pix;
        g_idx[rid] = ii;
        g_wgt[rid] = ww;
    }
}

// ---------------------------------------------------------------------------
// Kernel B: fused deformable sampling + GEMM + bias + relu
// grid: (H, B), block: 128 threads (one pixel per thread), acc[64] in regs
// ---------------------------------------------------------------------------
__global__ __launch_bounds__(WW) void kdeform(const float* __restrict__ x,
                                              const float* __restrict__ b_def,
                                              float* __restrict__ out) {
    const int w = threadIdx.x;
    const int h = blockIdx.x;
    const int b = blockIdx.y;
    const int pix = h * WW + w;

    __shared__ float wk[CC * OO];   // w_def slice for current tap: [c][o], 16 KB

    float acc[OO];
#pragma unroll
    for (int o = 0; o < OO; o++) acc[o] = 0.f;

    const float* xb = x + (size_t)b * CC * HW;

    for (int k = 0; k < K2; k++) {
        __syncthreads();
        for (int i = threadIdx.x; i < CC * OO; i += WW)
            wk[i] = g_wdef_t[k * (CC * OO) + i];
        __syncthreads();

        const int rid = (b * K2 + k) * HW + pix;
        const int4   ii = g_idx[rid];
        const float4 ww = g_wgt[rid];

#pragma unroll 2
        for (int c = 0; c < CC; c++) {
            const float* xc = xb + c * HW;
            float col = ww.x * __ldg(xc + ii.x)
                      + ww.y * __ldg(xc + ii.y)
                      + ww.z * __ldg(xc + ii.z)
                      + ww.w * __ldg(xc + ii.w);
            const float* wrow = &wk[c * OO];
#pragma unroll
            for (int o = 0; o < OO; o++) acc[o] += col * wrow[o];
        }
    }

#pragma unroll
    for (int o = 0; o < OO; o++) {
        float r = acc[o] + b_def[o];
        out[((size_t)(b * OO + o)) * HW + pix] = fmaxf(r, 0.f);
    }
}

// ---------------------------------------------------------------------------
extern "C" void kernel_launch(void* const* d_in, const int* in_sizes, int n_in,
                              void* d_out, int out_size) {
    const float* x     = (const float*)d_in[0];
    const float* feat  = (const float*)d_in[1];
    const float* w_off = (const float*)d_in[2];
    const float* b_off = (const float*)d_in[3];
    const float* w_def = (const float*)d_in[4];
    const float* b_def = (const float*)d_in[5];
    float* out = (float*)d_out;

    ktranspose<<<(K2 * CC * OO + 255) / 256, 256>>>(w_off, w_def);

    dim3 grid(HH, BB);
    koffset<<<grid, WW>>>(feat, b_off);
    kdeform<<<grid, WW>>>(x, b_def, out);
}